// round 11
// baseline (speedup 1.0000x reference)
#include <cuda_runtime.h>

// mean(cumsum(per_sample)) == (1/B) * sum_i per_sample[i] * (B - i)
// Single-pass weighted reduction; single kernel, last-block finalize.
// 256-bit loads (ld.global.nc.v8.f32, sm_100a): one load = one full
// 8-channel sample row per lane. GRID = 888 = 148 * 6 -> one wave.

#define WBCE_EPS 1e-10f
#define GRID_MAIN 888
#define THREADS_MAIN 256

__device__ double g_partials[GRID_MAIN];
__device__ unsigned int g_done = 0;   // self-resets via atomicInc wraparound

struct F8 { float v0, v1, v2, v3, v4, v5, v6, v7; };

__device__ __forceinline__ F8 ldg256(const float* p) {
    F8 r;
    asm volatile("ld.global.nc.v8.f32 {%0,%1,%2,%3,%4,%5,%6,%7}, [%8];"
                 : "=f"(r.v0), "=f"(r.v1), "=f"(r.v2), "=f"(r.v3),
                   "=f"(r.v4), "=f"(r.v5), "=f"(r.v6), "=f"(r.v7)
                 : "l"(p));
    return r;
}

__device__ __forceinline__ float elem_term(float l, float t, float wP, float wN) {
    // t is exactly 0.0f or 1.0f; dead branch contributes exactly 0
    bool pos = (t != 0.0f);
    float x = pos ? l : (1.0f - l);
    float w = pos ? wP : wN;
    return w * __logf(x + WBCE_EPS);
}

__global__ __launch_bounds__(THREADS_MAIN, 6) void wbce_fused_kernel(
    const float* __restrict__ logits,
    const float* __restrict__ targets,
    const float* __restrict__ wp,
    const float* __restrict__ wn,
    float* __restrict__ out,
    int B)   // number of rows = 2^23, fits int32
{
    __shared__ float swp[8];
    __shared__ float swn[8];
    if (threadIdx.x < 8) {
        swp[threadIdx.x] = wp[threadIdx.x];
        swn[threadIdx.x] = wn[threadIdx.x];
    }
    __syncthreads();

    const float w0p = swp[0], w1p = swp[1], w2p = swp[2], w3p = swp[3];
    const float w4p = swp[4], w5p = swp[5], w6p = swp[6], w7p = swp[7];
    const float w0n = swn[0], w1n = swn[1], w2n = swn[2], w3n = swn[3];
    const float w4n = swn[4], w5n = swn[5], w6n = swn[6], w7n = swn[7];

    const int stride = GRID_MAIN * THREADS_MAIN;            // rows per step
    const int tid = blockIdx.x * THREADS_MAIN + threadIdx.x;

    // Row weight (B - row): integer <= 2^23, exact in fp32 throughout.
    float wrow = (float)(B - tid);
    const float wstep = (float)stride;

    double acc = 0.0;
    for (int row = tid; row < B; row += stride) {
        F8 l = ldg256(logits + (size_t)row * 8);
        F8 t = ldg256(targets + (size_t)row * 8);

        float s = elem_term(l.v0, t.v0, w0p, w0n)
                + elem_term(l.v1, t.v1, w1p, w1n)
                + elem_term(l.v2, t.v2, w2p, w2n)
                + elem_term(l.v3, t.v3, w3p, w3n)
                + elem_term(l.v4, t.v4, w4p, w4n)
                + elem_term(l.v5, t.v5, w5p, w5n)
                + elem_term(l.v6, t.v6, w6p, w6n)
                + elem_term(l.v7, t.v7, w7p, w7n);

        acc -= (double)(wrow * s);   // one double add per row
        wrow -= wstep;
    }

    // ---- block reduce (double) ----
    #pragma unroll
    for (int off = 16; off > 0; off >>= 1)
        acc += __shfl_down_sync(0xffffffffu, acc, off);

    __shared__ double ssum[THREADS_MAIN / 32];
    const int warp = threadIdx.x >> 5;
    if ((threadIdx.x & 31) == 0) ssum[warp] = acc;
    __syncthreads();

    // ---- last-block finalize ----
    __shared__ bool s_last;
    if (threadIdx.x == 0) {
        double b = 0.0;
        #pragma unroll
        for (int w = 0; w < THREADS_MAIN / 32; w++) b += ssum[w];
        g_partials[blockIdx.x] = b;
        __threadfence();
        unsigned int old = atomicInc(&g_done, GRID_MAIN - 1);  // wraps to 0
        s_last = (old == GRID_MAIN - 1);
    }
    __syncthreads();

    if (s_last) {
        __threadfence();
        volatile double* vp = g_partials;
        double a = 0.0;
        for (int i = threadIdx.x; i < GRID_MAIN; i += THREADS_MAIN)
            a += vp[i];

        #pragma unroll
        for (int off = 16; off > 0; off >>= 1)
            a += __shfl_down_sync(0xffffffffu, a, off);

        if ((threadIdx.x & 31) == 0) ssum[warp] = a;
        __syncthreads();

        if (threadIdx.x == 0) {
            double tot = 0.0;
            #pragma unroll
            for (int w = 0; w < THREADS_MAIN / 32; w++) tot += ssum[w];
            out[0] = (float)(tot / (double)B);
        }
    }
}

extern "C" void kernel_launch(void* const* d_in, const int* in_sizes, int n_in,
                              void* d_out, int out_size) {
    const float* logits  = (const float*)d_in[0];
    const float* targets = (const float*)d_in[1];
    const float* wp      = (const float*)d_in[2];
    const float* wn      = (const float*)d_in[3];

    const int n_elem = in_sizes[0];   // B * 8 = 2^26, fits int32
    const int B = n_elem >> 3;        // rows

    wbce_fused_kernel<<<GRID_MAIN, THREADS_MAIN>>>(logits, targets, wp, wn,
                                                   (float*)d_out, B);
}

// round 12
// speedup vs baseline: 1.2965x; 1.2965x over previous
#include <cuda_runtime.h>

// mean(cumsum(per_sample)) == (1/B) * sum_i per_sample[i] * (B - i)
// Single-pass weighted reduction; single kernel, last-block finalize.
// GRID = 888 = 148 SMs * 6 blocks (<=40 regs via launch_bounds, 256 thr)
// -> exactly ONE wave at 48 warps/SM. Plain __ldg LDG.128 loads:
// measured best (81.95us, DRAM 81%). Streaming cache-ops (+4us),
// chunk-stealing (+14us) and v8.f32 loads (+24us) all regressed.

#define WBCE_EPS 1e-10f
#define GRID_MAIN 888
#define THREADS_MAIN 256

__device__ double g_partials[GRID_MAIN];
__device__ unsigned int g_done = 0;   // self-resets via atomicInc wraparound

__device__ __forceinline__ float elem_term(float l, float t, float wP, float wN) {
    // t is exactly 0.0f or 1.0f; dead branch contributes exactly 0
    bool pos = (t != 0.0f);
    float x = pos ? l : (1.0f - l);
    float w = pos ? wP : wN;
    return w * __logf(x + WBCE_EPS);
}

__global__ __launch_bounds__(THREADS_MAIN, 6) void wbce_fused_kernel(
    const float* __restrict__ logits,
    const float* __restrict__ targets,
    const float* __restrict__ wp,
    const float* __restrict__ wn,
    float* __restrict__ out,
    int N4)   // float4 groups = B*2 (C=8 -> 2 groups per row), fits int32
{
    __shared__ float swp[8];
    __shared__ float swn[8];
    if (threadIdx.x < 8) {
        swp[threadIdx.x] = wp[threadIdx.x];
        swn[threadIdx.x] = wn[threadIdx.x];
    }
    __syncthreads();

    const int stride = GRID_MAIN * THREADS_MAIN;            // even
    const int tid = blockIdx.x * THREADS_MAIN + threadIdx.x;

    // Channel half (0..3 or 4..7) fixed per thread (stride even).
    const int cb = (tid & 1) * 4;
    const float w0p = swp[cb + 0], w1p = swp[cb + 1], w2p = swp[cb + 2], w3p = swp[cb + 3];
    const float w0n = swn[cb + 0], w1n = swn[cb + 1], w2n = swn[cb + 2], w3n = swn[cb + 3];

    const float4* __restrict__ lg = (const float4*)logits;
    const float4* __restrict__ tg = (const float4*)targets;

    const int B = N4 >> 1;
    // Row weight (B - i): integer <= 2^23, exact in fp32 throughout.
    float wrow = (float)(B - (tid >> 1));
    const float wstep = (float)(stride >> 1);

    double acc = 0.0;
    int idx = tid;

    // Unroll x2: 4 independent LDG.128 in flight per thread.
    for (; idx + stride < N4; idx += 2 * stride) {
        float4 l0 = __ldg(lg + idx);
        float4 t0 = __ldg(tg + idx);
        float4 l1 = __ldg(lg + idx + stride);
        float4 t1 = __ldg(tg + idx + stride);

        float s0 = elem_term(l0.x, t0.x, w0p, w0n)
                 + elem_term(l0.y, t0.y, w1p, w1n)
                 + elem_term(l0.z, t0.z, w2p, w2n)
                 + elem_term(l0.w, t0.w, w3p, w3n);
        float s1 = elem_term(l1.x, t1.x, w0p, w0n)
                 + elem_term(l1.y, t1.y, w1p, w1n)
                 + elem_term(l1.z, t1.z, w2p, w2n)
                 + elem_term(l1.w, t1.w, w3p, w3n);

        // wrow*s0 + (wrow - wstep)*s1, all fp32; one double add per pair.
        float prod = fmaf(wrow, s0, (wrow - wstep) * s1);
        acc -= (double)prod;
        wrow -= 2.0f * wstep;
    }
    if (idx < N4) {
        float4 l0 = __ldg(lg + idx);
        float4 t0 = __ldg(tg + idx);
        float s0 = elem_term(l0.x, t0.x, w0p, w0n)
                 + elem_term(l0.y, t0.y, w1p, w1n)
                 + elem_term(l0.z, t0.z, w2p, w2n)
                 + elem_term(l0.w, t0.w, w3p, w3n);
        acc -= (double)(wrow * s0);
    }

    // ---- block reduce (double) ----
    #pragma unroll
    for (int off = 16; off > 0; off >>= 1)
        acc += __shfl_down_sync(0xffffffffu, acc, off);

    __shared__ double ssum[THREADS_MAIN / 32];
    const int warp = threadIdx.x >> 5;
    if ((threadIdx.x & 31) == 0) ssum[warp] = acc;
    __syncthreads();

    // ---- last-block finalize ----
    __shared__ bool s_last;
    if (threadIdx.x == 0) {
        double b = 0.0;
        #pragma unroll
        for (int w = 0; w < THREADS_MAIN / 32; w++) b += ssum[w];
        g_partials[blockIdx.x] = b;
        __threadfence();
        unsigned int old = atomicInc(&g_done, GRID_MAIN - 1);  // wraps to 0
        s_last = (old == GRID_MAIN - 1);
    }
    __syncthreads();

    if (s_last) {
        __threadfence();
        volatile double* vp = g_partials;
        double a = 0.0;
        for (int i = threadIdx.x; i < GRID_MAIN; i += THREADS_MAIN)
            a += vp[i];

        #pragma unroll
        for (int off = 16; off > 0; off >>= 1)
            a += __shfl_down_sync(0xffffffffu, a, off);

        if ((threadIdx.x & 31) == 0) ssum[warp] = a;
        __syncthreads();

        if (threadIdx.x == 0) {
            double tot = 0.0;
            #pragma unroll
            for (int w = 0; w < THREADS_MAIN / 32; w++) tot += ssum[w];
            out[0] = (float)(tot / (double)B);
        }
    }
}

extern "C" void kernel_launch(void* const* d_in, const int* in_sizes, int n_in,
                              void* d_out, int out_size) {
    const float* logits  = (const float*)d_in[0];
    const float* targets = (const float*)d_in[1];
    const float* wp      = (const float*)d_in[2];
    const float* wn      = (const float*)d_in[3];

    const int n_elem = in_sizes[0];   // B * 8 = 2^26, fits int32
    const int N4 = n_elem >> 2;       // float4 groups

    wbce_fused_kernel<<<GRID_MAIN, THREADS_MAIN>>>(logits, targets, wp, wn,
                                                   (float*)d_out, N4);
}